// round 16
// baseline (speedup 1.0000x reference)
#include <cuda_runtime.h>
#include <cuda_fp16.h>
#include <cstdint>

// Problem constants (fixed by the dataset)
#define BB 4
#define CC 256
#define HW 4096

#define CHW_C  (1048576LL)          // CC*HW
#define SHW_C  (16777216LL)         // HW*HW
#define MEW_C  (2097152LL)          // HW*2*CC

// ---------------- scratch (no allocations allowed -> device globals) -------
__device__ __half g_Xth[(size_t)3 * BB * HW * CC];    // [inp][b][p][c] hi
__device__ __half g_Xtl[(size_t)3 * BB * HW * CC];    // [inp][b][p][c] lo
__device__ __half g_Wsh[3 * CC * CC];                 // [w][o][c] hi
__device__ __half g_Wsl[3 * CC * CC];                 // [w][o][c] lo
__device__ __half g_Qh [(size_t)BB * HW * CC];
__device__ __half g_Ql [(size_t)BB * HW * CC];
__device__ __half g_Kth[(size_t)BB * HW * CC];
__device__ __half g_Ktl[(size_t)BB * HW * CC];
__device__ __half g_VVth[(size_t)BB * 2 * CC * HW];
__device__ __half g_VVtl[(size_t)BB * 2 * CC * HW];
__device__ __half g_Sh [(size_t)BB * HW * HW];
__device__ __half g_Sl [(size_t)BB * HW * HW];
__device__ float  g_S  [(size_t)BB * HW * HW];        // fp32 logits
__device__ float  g_ME [(size_t)BB * HW * 2 * CC];    // [b][n][mean|E2]
__device__ float  g_cmean[BB * CC];
__device__ float  g_cinv [BB * CC];

// =========================== PTX helpers (baseline, sm_80+) ================
#define LDSM4(r, addr) \
    asm volatile("ldmatrix.sync.aligned.m8n8.x4.shared.b16 {%0,%1,%2,%3}, [%4];" \
        : "=r"((r)[0]), "=r"((r)[1]), "=r"((r)[2]), "=r"((r)[3]) : "r"(addr))

#define MMA16816(d, a, b0, b1) \
    asm volatile("mma.sync.aligned.m16n8k16.row.col.f32.f16.f16.f32 " \
        "{%0,%1,%2,%3}, {%4,%5,%6,%7}, {%8,%9}, {%0,%1,%2,%3};" \
        : "+f"((d)[0]), "+f"((d)[1]), "+f"((d)[2]), "+f"((d)[3]) \
        : "r"((a)[0]), "r"((a)[1]), "r"((a)[2]), "r"((a)[3]), "r"(b0), "r"(b1))

// fp16-accumulate variant (used only for tiny correction terms)
#define MMA16816H(d, a, b0, b1) \
    asm volatile("mma.sync.aligned.m16n8k16.row.col.f16.f16.f16.f16 " \
        "{%0,%1}, {%2,%3,%4,%5}, {%6,%7}, {%0,%1};" \
        : "+r"((d)[0]), "+r"((d)[1]) \
        : "r"((a)[0]), "r"((a)[1]), "r"((a)[2]), "r"((a)[3]), "r"(b0), "r"(b1))

#define CP16(dst, src) \
    asm volatile("cp.async.cg.shared.global [%0], [%1], 16;" :: "r"(dst), "l"(src))
#define CP_COMMIT() asm volatile("cp.async.commit_group;" ::: "memory")
#define CP_WAIT1()  asm volatile("cp.async.wait_group 1;" ::: "memory")
#define CP_WAIT0()  asm volatile("cp.async.wait_group 0;" ::: "memory")

__device__ __forceinline__ void split2(float a, float b, uint32_t& hi, uint32_t& lo) {
    __half h0 = __float2half_rn(a), h1 = __float2half_rn(b);
    __half l0 = __float2half_rn(a - __half2float(h0));
    __half l1 = __float2half_rn(b - __half2float(h1));
    __half2 H = __halves2half2(h0, h1), L = __halves2half2(l0, l1);
    hi = *reinterpret_cast<uint32_t*>(&H);
    lo = *reinterpret_cast<uint32_t*>(&L);
}

// ===========================================================================
// HMMA split GEMM on pre-split fp16:  C = A @ B^T     (all geometry constexpr)
// CTA 128(M) x 64(N), 8 warps (4M x 2N), warp tile 32x32, k-step 64.
// 2-stage cp.async, 96 KB SMEM/CTA -> 2 CTAs/SM, prefetch depth 2.
// 3 passes: aH*bH (fp32 acc) + aL*bH + aH*bL (fp16 acc, tiny error terms)
// EPI 0: fp32 store; EPI 1: bias[col]+split (Q,Kt); EPI 2: bias[row]+split+sq
// grid = (N/64, M/128, batch)  [batch chains pass pre-offset pointers, z=1]
// ===========================================================================
#define STAGE_BYTES 49152
#define OFF_AH 0
#define OFF_AL 16384
#define OFF_BH 32768
#define OFF_BL 40960

template <int EPI, int K, int LDC, long long STRA, long long STRB, long long STRC>
__global__ void __launch_bounds__(256, 2) hmma6(
    const __half* __restrict__ Ah, const __half* __restrict__ Al,
    const __half* __restrict__ Bh, const __half* __restrict__ Bl,
    float* __restrict__ Cf, __half* __restrict__ OH, __half* __restrict__ OL,
    const float* __restrict__ bias)
{
    extern __shared__ char smem[];
    const uint32_t uS = (uint32_t)__cvta_generic_to_shared(smem);

    const int tid  = threadIdx.x;
    const int lane = tid & 31;
    const int wid  = tid >> 5;
    const int wm   = wid & 3;    // 0..3: 32 M-rows each
    const int wn   = wid >> 2;   // 0..1: 32 N-cols each

    const long long aoff = blockIdx.z * STRA + (long long)(blockIdx.y * 128) * K;
    const long long boff = blockIdx.z * STRB + (long long)(blockIdx.x * 64) * K;
    Ah += aoff; Al += aoff; Bh += boff; Bl += boff;
    const long long coff = blockIdx.z * STRC +
        (long long)(blockIdx.y * 128) * LDC + blockIdx.x * 64;
    if (EPI == 0) { Cf += coff; } else { OH += coff; OL += coff; }
    if (EPI == 1) bias += blockIdx.x * 64;
    if (EPI == 2) bias += blockIdx.y * 128;

    // cp.async mapping: fixed 16B chunk column per thread
    const int lr  = tid >> 3;        // 0..31
    const int col = tid & 7;
    const uint32_t dst0 = lr * 128 + ((col * 16) ^ ((lr & 7) << 4));
    const __half* tAh = Ah + (size_t)lr * K + col * 8;
    const __half* tAl = Al + (size_t)lr * K + col * 8;
    const __half* tBh = Bh + (size_t)lr * K + col * 8;
    const __half* tBl = Bl + (size_t)lr * K + col * 8;

    auto load_stage = [&](int stage, int k0) {
        const uint32_t sb = uS + stage * STAGE_BYTES + dst0;
#pragma unroll
        for (int i = 0; i < 4; i++) {
            const size_t go = (size_t)i * 32 * K + k0;
            CP16(sb + OFF_AH + i * 4096, tAh + go);
            CP16(sb + OFF_AL + i * 4096, tAl + go);
        }
#pragma unroll
        for (int i = 0; i < 2; i++) {
            const size_t go = (size_t)i * 32 * K + k0;
            CP16(sb + OFF_BH + i * 4096, tBh + go);
            CP16(sb + OFF_BL + i * 4096, tBl + go);
        }
        CP_COMMIT();
    };

    float acc[2][4][4];
    uint32_t acc16[2][4][2];
#pragma unroll
    for (int i = 0; i < 2; i++)
#pragma unroll
        for (int j = 0; j < 4; j++) {
#pragma unroll
            for (int t = 0; t < 4; t++) acc[i][j][t] = 0.f;
            acc16[i][j][0] = 0u; acc16[i][j][1] = 0u;
        }

    constexpr int NK = K >> 6;
    load_stage(0, 0);
    if (NK > 1) load_stage(1, 64);

    const int grp  = lane >> 3;
    const int lrow = lane & 7;
    const int abase = wm * 32 + lrow + ((grp & 1) << 3);
    const int bbase = wn * 32 + lrow + ((grp & 1) << 3);

    for (int ks = 0; ks < NK; ks++) {
        if (ks + 1 < NK) CP_WAIT1(); else CP_WAIT0();
        __syncthreads();

        const uint32_t sb = uS + (ks & 1) * STAGE_BYTES;
#pragma unroll
        for (int ksub = 0; ksub < 4; ksub++) {
            const int colb = (ksub * 2 + (grp >> 1)) * 16;
            uint32_t aH[2][4], aL[2][4];
#pragma unroll
            for (int mt = 0; mt < 2; mt++) {
                const int row = abase + mt * 16;
                const uint32_t off = row * 128 + (colb ^ ((row & 7) << 4));
                LDSM4(aH[mt], sb + OFF_AH + off);
                LDSM4(aL[mt], sb + OFF_AL + off);
            }
#pragma unroll
            for (int nt4 = 0; nt4 < 2; nt4++) {
                const int brow = bbase + nt4 * 16;
                const uint32_t boff2 = brow * 128 + (colb ^ ((brow & 7) << 4));
                uint32_t bh[4], bl[4];
                LDSM4(bh, sb + OFF_BH + boff2);
                LDSM4(bl, sb + OFF_BL + boff2);
                // main pass: fp32 accumulate
#pragma unroll
                for (int mt = 0; mt < 2; mt++) {
                    MMA16816(acc[mt][nt4 * 2],     aH[mt], bh[0], bh[2]);
                    MMA16816(acc[mt][nt4 * 2 + 1], aH[mt], bh[1], bh[3]);
                }
                // correction passes: fp16 acc, mt-major so same-reg RAW >= 4 MMAs
#pragma unroll
                for (int mt = 0; mt < 2; mt++) {
                    MMA16816H(acc16[mt][nt4 * 2],     aL[mt], bh[0], bh[2]);
                    MMA16816H(acc16[mt][nt4 * 2 + 1], aL[mt], bh[1], bh[3]);
                }
#pragma unroll
                for (int mt = 0; mt < 2; mt++) {
                    MMA16816H(acc16[mt][nt4 * 2],     aH[mt], bl[0], bl[2]);
                    MMA16816H(acc16[mt][nt4 * 2 + 1], aH[mt], bl[1], bl[3]);
                }
            }
        }
        __syncthreads();
        if (ks + 2 < NK) load_stage(ks & 1, (ks + 2) * 64);
    }

    // ---- epilogue ----
#pragma unroll
    for (int mt = 0; mt < 2; mt++) {
        const int lr2 = wm * 32 + mt * 16 + (lane >> 2);
#pragma unroll
        for (int nt = 0; nt < 4; nt++) {
            const int c2 = wn * 32 + nt * 8 + (lane & 3) * 2;
            const __half2 e0 = *reinterpret_cast<__half2*>(&acc16[mt][nt][0]);
            const __half2 e1 = *reinterpret_cast<__half2*>(&acc16[mt][nt][1]);
            float v00 = acc[mt][nt][0] + __low2float(e0);
            float v01 = acc[mt][nt][1] + __high2float(e0);
            float v10 = acc[mt][nt][2] + __low2float(e1);
            float v11 = acc[mt][nt][3] + __high2float(e1);
            if (EPI == 0) {
                *reinterpret_cast<float2*>(Cf + (long long)lr2 * LDC + c2) =
                    make_float2(v00, v01);
                *reinterpret_cast<float2*>(Cf + (long long)(lr2 + 8) * LDC + c2) =
                    make_float2(v10, v11);
            } else if (EPI == 1) {
                const float b0 = bias[c2], b1 = bias[c2 + 1];
                uint32_t h, l;
                split2(v00 + b0, v01 + b1, h, l);
                *reinterpret_cast<uint32_t*>(OH + (long long)lr2 * LDC + c2) = h;
                *reinterpret_cast<uint32_t*>(OL + (long long)lr2 * LDC + c2) = l;
                split2(v10 + b0, v11 + b1, h, l);
                *reinterpret_cast<uint32_t*>(OH + (long long)(lr2 + 8) * LDC + c2) = h;
                *reinterpret_cast<uint32_t*>(OL + (long long)(lr2 + 8) * LDC + c2) = l;
            } else {
                const float b0 = bias[lr2], b1 = bias[lr2 + 8];
                float t0 = v00 + b0, t1 = v01 + b0;
                float t2 = v10 + b1, t3 = v11 + b1;
                uint32_t h, l;
                split2(t0, t1, h, l);
                *reinterpret_cast<uint32_t*>(OH + (long long)lr2 * LDC + c2) = h;
                *reinterpret_cast<uint32_t*>(OL + (long long)lr2 * LDC + c2) = l;
                split2(t0 * t0, t1 * t1, h, l);
                *reinterpret_cast<uint32_t*>(OH + (long long)(lr2 + 256) * LDC + c2) = h;
                *reinterpret_cast<uint32_t*>(OL + (long long)(lr2 + 256) * LDC + c2) = l;
                split2(t2, t3, h, l);
                *reinterpret_cast<uint32_t*>(OH + (long long)(lr2 + 8) * LDC + c2) = h;
                *reinterpret_cast<uint32_t*>(OL + (long long)(lr2 + 8) * LDC + c2) = l;
                split2(t2 * t2, t3 * t3, h, l);
                *reinterpret_cast<uint32_t*>(OH + (long long)(lr2 + 264) * LDC + c2) = h;
                *reinterpret_cast<uint32_t*>(OL + (long long)(lr2 + 264) * LDC + c2) = l;
            }
        }
    }
}

// ===========================================================================
// Transpose + split: X [b][c][p] fp32 -> Xt hi/lo [inp][b][p][c] halves.
// grid (HW/32, CC/32, 12): z -> (inp = z>>2, b = z&3). 32x32 SMEM tiles.
// ===========================================================================
__global__ __launch_bounds__(256) void tsplit_k(
    const float* __restrict__ ckey, const float* __restrict__ skey,
    const float* __restrict__ style)
{
    __shared__ float s[32][33];
    const int p = blockIdx.z >> 2;
    const int b = blockIdx.z & 3;
    const long long CHW = CHW_C;

    const float* src = (p == 0) ? ckey : (p == 1) ? skey : style;
    src += b * CHW;
    __half* dh = g_Xth + p * (BB * CHW) + b * CHW;
    __half* dl = g_Xtl + p * (BB * CHW) + b * CHW;

    const int tid = threadIdx.x;
    const int c0 = blockIdx.y * 32;
    const int p0 = blockIdx.x * 32;

    {
        const int cr = tid >> 3;
        const int pc = (tid & 7) * 4;
        float4 v = *reinterpret_cast<const float4*>(
            src + (long long)(c0 + cr) * HW + p0 + pc);
        s[cr][pc + 0] = v.x; s[cr][pc + 1] = v.y;
        s[cr][pc + 2] = v.z; s[cr][pc + 3] = v.w;
    }
    __syncthreads();
    {
        const int pr = tid >> 3;
        const int cc = (tid & 7) * 4;
        float a0 = s[cc + 0][pr], a1 = s[cc + 1][pr];
        float a2 = s[cc + 2][pr], a3 = s[cc + 3][pr];
        uint32_t h01, l01, h23, l23;
        split2(a0, a1, h01, l01);
        split2(a2, a3, h23, l23);
        const long long o = (long long)(p0 + pr) * CC + c0 + cc;
        *reinterpret_cast<uint2*>(dh + o) = make_uint2(h01, h23);
        *reinterpret_cast<uint2*>(dl + o) = make_uint2(l01, l23);
    }
}

// ---------------------------------------------------------------------------
__global__ __launch_bounds__(256) void wsplit_k(
    const float* __restrict__ Wf, const float* __restrict__ Wg,
    const float* __restrict__ Whp)
{
    const int w = blockIdx.y;
    const float* src = (w == 0) ? Wf : (w == 1) ? Wg : Whp;
    const int i4 = (blockIdx.x * 256 + threadIdx.x) * 4;
    float4 v = *reinterpret_cast<const float4*>(src + i4);
    uint32_t h01, l01, h23, l23;
    split2(v.x, v.y, h01, l01);
    split2(v.z, v.w, h23, l23);
    const int o = w * (CC * CC) + i4;
    *reinterpret_cast<uint2*>(g_Wsh + o) = make_uint2(h01, h23);
    *reinterpret_cast<uint2*>(g_Wsl + o) = make_uint2(l01, l23);
}

// ---------------------------------------------------------------------------
// Row softmax over 4096 cols for rows [rowbase, rowbase+grid).
// ---------------------------------------------------------------------------
__global__ __launch_bounds__(256) void softmax_k(int rowbase)
{
    __shared__ float red[8];
    const size_t row = rowbase + blockIdx.x;
    const float4* p = reinterpret_cast<const float4*>(g_S + row * (size_t)HW);
    uint2* ph = reinterpret_cast<uint2*>(g_Sh + row * (size_t)HW);
    uint2* pl = reinterpret_cast<uint2*>(g_Sl + row * (size_t)HW);
    const int tid = threadIdx.x;

    float4 v[4];
    float mx = -3.4e38f;
#pragma unroll
    for (int i = 0; i < 4; i++) {
        v[i] = p[tid + i * 256];
        mx = fmaxf(mx, fmaxf(fmaxf(v[i].x, v[i].y), fmaxf(v[i].z, v[i].w)));
    }
#pragma unroll
    for (int o = 16; o > 0; o >>= 1)
        mx = fmaxf(mx, __shfl_xor_sync(0xffffffffu, mx, o));
    if ((tid & 31) == 0) red[tid >> 5] = mx;
    __syncthreads();
    mx = red[0];
#pragma unroll
    for (int i = 1; i < 8; i++) mx = fmaxf(mx, red[i]);

    float s = 0.f;
#pragma unroll
    for (int i = 0; i < 4; i++) {
        v[i].x = __expf(v[i].x - mx); v[i].y = __expf(v[i].y - mx);
        v[i].z = __expf(v[i].z - mx); v[i].w = __expf(v[i].w - mx);
        s += v[i].x + v[i].y + v[i].z + v[i].w;
    }
#pragma unroll
    for (int o = 16; o > 0; o >>= 1)
        s += __shfl_xor_sync(0xffffffffu, s, o);
    __syncthreads();
    if ((tid & 31) == 0) red[tid >> 5] = s;
    __syncthreads();
    s = red[0];
#pragma unroll
    for (int i = 1; i < 8; i++) s += red[i];

    const float inv = 1.0f / s;
#pragma unroll
    for (int i = 0; i < 4; i++) {
        float w0 = v[i].x * inv, w1 = v[i].y * inv;
        float w2 = v[i].z * inv, w3 = v[i].w * inv;
        uint32_t h01, l01, h23, l23;
        split2(w0, w1, h01, l01);
        split2(w2, w3, h23, l23);
        ph[tid + i * 256] = make_uint2(h01, h23);
        pl[tid + i * 256] = make_uint2(l01, l23);
    }
}

// ---------------------------------------------------------------------------
__global__ __launch_bounds__(256) void stats_k(const float* __restrict__ content)
{
    __shared__ float r1[8];
    __shared__ float r2[8];
    const int bc = blockIdx.x;
    const float4* p = reinterpret_cast<const float4*>(content + (size_t)bc * HW);
    const int tid = threadIdx.x;

    float s = 0.f, s2 = 0.f;
#pragma unroll
    for (int i = 0; i < 4; i++) {
        float4 v = p[tid + i * 256];
        s  += v.x + v.y + v.z + v.w;
        s2 += v.x * v.x + v.y * v.y + v.z * v.z + v.w * v.w;
    }
#pragma unroll
    for (int o = 16; o > 0; o >>= 1) {
        s  += __shfl_xor_sync(0xffffffffu, s, o);
        s2 += __shfl_xor_sync(0xffffffffu, s2, o);
    }
    if ((tid & 31) == 0) { r1[tid >> 5] = s; r2[tid >> 5] = s2; }
    __syncthreads();
    if (tid == 0) {
        float ts = 0.f, ts2 = 0.f;
#pragma unroll
        for (int i = 0; i < 8; i++) { ts += r1[i]; ts2 += r2[i]; }
        float mean = ts * (1.0f / HW);
        float var  = (ts2 - (float)HW * mean * mean) * (1.0f / (HW - 1));
        g_cmean[bc] = mean;
        g_cinv[bc]  = rsqrtf(var + 1e-5f);
    }
}

// ---------------------------------------------------------------------------
// Fused modulation, tiled transpose for coalesced ME reads and out writes.
// grid (HW/128, CC/32, BB), block 256.
// ---------------------------------------------------------------------------
__global__ __launch_bounds__(256) void final_k(const float* __restrict__ content,
                                               float* __restrict__ out)
{
    __shared__ float sM[128][33];
    __shared__ float sE[128][33];
    const int tid = threadIdx.x;
    const int b  = blockIdx.z;
    const int c0 = blockIdx.y * 32;
    const int n0 = blockIdx.x * 128;

    const float* base = g_ME + ((size_t)(b * HW + n0)) * (2 * CC) + c0;
    const int nl0 = tid >> 3;
    const int cq  = (tid & 7) * 4;
#pragma unroll
    for (int i = 0; i < 4; i++) {
        const int n = nl0 + i * 32;
        float4 m = *reinterpret_cast<const float4*>(base + (size_t)n * (2 * CC) + cq);
        float4 e = *reinterpret_cast<const float4*>(base + (size_t)n * (2 * CC) + CC + cq);
        sM[n][cq + 0] = m.x; sM[n][cq + 1] = m.y; sM[n][cq + 2] = m.z; sM[n][cq + 3] = m.w;
        sE[n][cq + 0] = e.x; sE[n][cq + 1] = e.y; sE[n][cq + 2] = e.z; sE[n][cq + 3] = e.w;
    }
    __syncthreads();

#pragma unroll
    for (int j = 0; j < 16; j++) {
        const int e  = j * 256 + tid;
        const int cl = e >> 7;
        const int nl = e & 127;
        const int c  = c0 + cl;
        const int bc = b * CC + c;
        const size_t oidx = ((size_t)bc) * HW + n0 + nl;
        const float m  = sM[nl][cl];
        const float e2 = sE[nl][cl];
        const float sd = sqrtf(fmaxf(e2 - m * m, 0.f));
        out[oidx] = sd * (content[oidx] - g_cmean[bc]) * g_cinv[bc] + m;
    }
}

// ---------------------------------------------------------------------------
extern "C" void kernel_launch(void* const* d_in, const int* in_sizes, int n_in,
                              void* d_out, int out_size)
{
    const float* content = (const float*)d_in[0];
    const float* style   = (const float*)d_in[1];
    const float* ckey    = (const float*)d_in[2];
    const float* skey    = (const float*)d_in[3];
    const float* Wf = (const float*)d_in[4];
    const float* bf = (const float*)d_in[5];
    const float* Wg = (const float*)d_in[6];
    const float* bg = (const float*)d_in[7];
    const float* Wh = (const float*)d_in[8];
    const float* bh = (const float*)d_in[9];
    float* out = (float*)d_out;

    __half *Xth, *Xtl, *Wsh, *Wsl;
    __half *Qh, *Ql, *Kth, *Ktl, *VVth, *VVtl, *Sh, *Sl;
    float *S, *ME;
    cudaGetSymbolAddress((void**)&Xth, g_Xth);
    cudaGetSymbolAddress((void**)&Xtl, g_Xtl);
    cudaGetSymbolAddress((void**)&Wsh, g_Wsh);
    cudaGetSymbolAddress((void**)&Wsl, g_Wsl);
    cudaGetSymbolAddress((void**)&Qh,  g_Qh);
    cudaGetSymbolAddress((void**)&Ql,  g_Ql);
    cudaGetSymbolAddress((void**)&Kth, g_Kth);
    cudaGetSymbolAddress((void**)&Ktl, g_Ktl);
    cudaGetSymbolAddress((void**)&VVth, g_VVth);
    cudaGetSymbolAddress((void**)&VVtl, g_VVtl);
    cudaGetSymbolAddress((void**)&Sh,  g_Sh);
    cudaGetSymbolAddress((void**)&Sl,  g_Sl);
    cudaGetSymbolAddress((void**)&S,   g_S);
    cudaGetSymbolAddress((void**)&ME,  g_ME);

    // Instantiations: <EPI, K, LDC, strA, strB, strC>
    auto kProj = hmma6<1, CC, CC, CHW_C, 0LL, CHW_C>;
    auto kVVt  = hmma6<2, CC, HW, 0LL, CHW_C, 2 * CHW_C>;
    auto kG1   = hmma6<0, CC, HW, CHW_C, CHW_C, SHW_C>;
    auto kG2   = hmma6<0, HW, 2 * CC, SHW_C, 2 * CHW_C, MEW_C>;

    // One-time setup (runs on the uncaptured correctness call).
    static cudaStream_t s1 = nullptr;
    static cudaEvent_t evFork = nullptr, evK = nullptr, evQ = nullptr;
    static cudaEvent_t evSide = nullptr, evDone = nullptr;
    if (s1 == nullptr) {
        cudaStreamCreateWithFlags(&s1, cudaStreamNonBlocking);
        cudaEventCreateWithFlags(&evFork, cudaEventDisableTiming);
        cudaEventCreateWithFlags(&evK,    cudaEventDisableTiming);
        cudaEventCreateWithFlags(&evQ,    cudaEventDisableTiming);
        cudaEventCreateWithFlags(&evSide, cudaEventDisableTiming);
        cudaEventCreateWithFlags(&evDone, cudaEventDisableTiming);
        cudaFuncSetAttribute(kProj, cudaFuncAttributeMaxDynamicSharedMemorySize,
                             2 * STAGE_BYTES);
        cudaFuncSetAttribute(kVVt, cudaFuncAttributeMaxDynamicSharedMemorySize,
                             2 * STAGE_BYTES);
        cudaFuncSetAttribute(kG1, cudaFuncAttributeMaxDynamicSharedMemorySize,
                             2 * STAGE_BYTES);
        cudaFuncSetAttribute(kG2, cudaFuncAttributeMaxDynamicSharedMemorySize,
                             2 * STAGE_BYTES);
    }

    const dim3 blk(256);
    const long long BCHW = (long long)BB * CHW_C;

    // ---- s0: input transpose+split and weight split ----
    tsplit_k<<<dim3(HW / 32, CC / 32, 12), blk>>>(ckey, skey, style);
    wsplit_k<<<dim3(64, 3), blk>>>(Wf, Wg, Wh);
    cudaEventRecord(evFork, 0);

    // ---- s1 (forked): Kt proj -> VVt proj -> content stats ----
    cudaStreamWaitEvent(s1, evFork, 0);
    kProj<<<dim3(4, 32, BB), blk, 2 * STAGE_BYTES, s1>>>(
        Xth + BCHW, Xtl + BCHW, Wsh + CC * CC, Wsl + CC * CC,
        nullptr, Kth, Ktl, bg);
    cudaEventRecord(evK, s1);
    kVVt<<<dim3(64, 2, BB), blk, 2 * STAGE_BYTES, s1>>>(
        Wsh + 2 * CC * CC, Wsl + 2 * CC * CC, Xth + 2 * BCHW, Xtl + 2 * BCHW,
        nullptr, VVth, VVtl, bh);
    stats_k<<<BB * CC, blk, 0, s1>>>(content);
    cudaEventRecord(evSide, s1);

    // ---- s0: Q proj ----
    kProj<<<dim3(4, 32, BB), blk, 2 * STAGE_BYTES>>>(
        Xth, Xtl, Wsh, Wsl, nullptr, Qh, Ql, bf);
    cudaEventRecord(evQ, 0);

    // Cross-join for batch chains: s0 needs Kt (evK); s1 needs Qh (evQ)
    // and its own VVt/stats are already stream-ordered.
    cudaStreamWaitEvent(0, evK, 0);
    cudaStreamWaitEvent(0, evSide, 0);   // G2(b0)/G2(b2) need VVt
    cudaStreamWaitEvent(s1, evQ, 0);

    // ---- per-batch chains: G1(b) -> softmax(b) -> G2(b), alternating ----
    for (int b = 0; b < BB; b++) {
        cudaStream_t sb = (b & 1) ? s1 : (cudaStream_t)0;
        kG1<<<dim3(64, 32, 1), blk, 2 * STAGE_BYTES, sb>>>(
            Qh + b * CHW_C, Ql + b * CHW_C, Kth + b * CHW_C, Ktl + b * CHW_C,
            S + b * SHW_C, nullptr, nullptr, nullptr);
        softmax_k<<<HW, blk, 0, sb>>>(b * HW);
        kG2<<<dim3(8, 32, 1), blk, 2 * STAGE_BYTES, sb>>>(
            Sh + b * SHW_C, Sl + b * SHW_C,
            VVth + b * 2 * CHW_C, VVtl + b * 2 * CHW_C,
            ME + b * MEW_C, nullptr, nullptr, nullptr);
    }

    // join s1 -> s0, then fused modulation
    cudaEventRecord(evDone, s1);
    cudaStreamWaitEvent(0, evDone, 0);
    final_k<<<dim3(HW / 128, CC / 32, BB), blk>>>(content, out);
}

// round 17
// speedup vs baseline: 1.0468x; 1.0468x over previous
#include <cuda_runtime.h>
#include <cuda_fp16.h>
#include <cstdint>

// Problem constants (fixed by the dataset)
#define BB 4
#define CC 256
#define HW 4096

#define CHW_C  (1048576LL)          // CC*HW
#define SHW_C  (16777216LL)         // HW*HW
#define MEW_C  (2097152LL)          // HW*2*CC

// ---------------- scratch (no allocations allowed -> device globals) -------
__device__ __half g_Xth[(size_t)3 * BB * HW * CC];    // [inp][b][p][c] hi
__device__ __half g_Xtl[(size_t)3 * BB * HW * CC];    // [inp][b][p][c] lo
__device__ __half g_Wsh[3 * CC * CC];                 // [w][o][c] hi
__device__ __half g_Wsl[3 * CC * CC];                 // [w][o][c] lo
__device__ __half g_Qh [(size_t)BB * HW * CC];
__device__ __half g_Ql [(size_t)BB * HW * CC];
__device__ __half g_Kth[(size_t)BB * HW * CC];
__device__ __half g_Ktl[(size_t)BB * HW * CC];
__device__ __half g_VVth[(size_t)BB * 2 * CC * HW];
__device__ __half g_VVtl[(size_t)BB * 2 * CC * HW];
__device__ __half g_Sh [(size_t)BB * HW * HW];
__device__ __half g_Sl [(size_t)BB * HW * HW];
__device__ float  g_S  [(size_t)BB * HW * HW];        // fp32 logits
__device__ float  g_ME [(size_t)BB * HW * 2 * CC];    // [b][n][mean|E2]
__device__ float  g_cmean[BB * CC];
__device__ float  g_cinv [BB * CC];

// =========================== PTX helpers (baseline, sm_80+) ================
#define LDSM4(r, addr) \
    asm volatile("ldmatrix.sync.aligned.m8n8.x4.shared.b16 {%0,%1,%2,%3}, [%4];" \
        : "=r"((r)[0]), "=r"((r)[1]), "=r"((r)[2]), "=r"((r)[3]) : "r"(addr))

#define MMA16816(d, a, b0, b1) \
    asm volatile("mma.sync.aligned.m16n8k16.row.col.f32.f16.f16.f32 " \
        "{%0,%1,%2,%3}, {%4,%5,%6,%7}, {%8,%9}, {%0,%1,%2,%3};" \
        : "+f"((d)[0]), "+f"((d)[1]), "+f"((d)[2]), "+f"((d)[3]) \
        : "r"((a)[0]), "r"((a)[1]), "r"((a)[2]), "r"((a)[3]), "r"(b0), "r"(b1))

// fp16-accumulate variant (used only for tiny correction terms)
#define MMA16816H(d, a, b0, b1) \
    asm volatile("mma.sync.aligned.m16n8k16.row.col.f16.f16.f16.f16 " \
        "{%0,%1}, {%2,%3,%4,%5}, {%6,%7}, {%0,%1};" \
        : "+r"((d)[0]), "+r"((d)[1]) \
        : "r"((a)[0]), "r"((a)[1]), "r"((a)[2]), "r"((a)[3]), "r"(b0), "r"(b1))

#define CP16(dst, src) \
    asm volatile("cp.async.cg.shared.global [%0], [%1], 16;" :: "r"(dst), "l"(src))
#define CP_COMMIT() asm volatile("cp.async.commit_group;" ::: "memory")
#define CP_WAIT1()  asm volatile("cp.async.wait_group 1;" ::: "memory")
#define CP_WAIT0()  asm volatile("cp.async.wait_group 0;" ::: "memory")

__device__ __forceinline__ void split2(float a, float b, uint32_t& hi, uint32_t& lo) {
    __half h0 = __float2half_rn(a), h1 = __float2half_rn(b);
    __half l0 = __float2half_rn(a - __half2float(h0));
    __half l1 = __float2half_rn(b - __half2float(h1));
    __half2 H = __halves2half2(h0, h1), L = __halves2half2(l0, l1);
    hi = *reinterpret_cast<uint32_t*>(&H);
    lo = *reinterpret_cast<uint32_t*>(&L);
}

// ===========================================================================
// HMMA split GEMM on pre-split fp16:  C = A @ B^T     (all geometry constexpr)
// CTA 128(M) x 64(N), 8 warps (4M x 2N), warp tile 32x32, k-step 64.
// 2-stage cp.async, 96 KB SMEM/CTA -> 2 CTAs/SM, prefetch depth 2.
// 3 passes: aH*bH (fp32 acc) + aL*bH + aH*bL (fp16 acc, tiny error terms)
// EPI 0: fp32 store; EPI 1: bias[col]+split (Q,Kt); EPI 2: bias[row]+split+sq
// grid = (N/64, M/128, batch)
// ===========================================================================
#define STAGE_BYTES 49152
#define OFF_AH 0
#define OFF_AL 16384
#define OFF_BH 32768
#define OFF_BL 40960

template <int EPI, int K, int LDC, long long STRA, long long STRB, long long STRC>
__global__ void __launch_bounds__(256, 2) hmma6(
    const __half* __restrict__ Ah, const __half* __restrict__ Al,
    const __half* __restrict__ Bh, const __half* __restrict__ Bl,
    float* __restrict__ Cf, __half* __restrict__ OH, __half* __restrict__ OL,
    const float* __restrict__ bias)
{
    extern __shared__ char smem[];
    const uint32_t uS = (uint32_t)__cvta_generic_to_shared(smem);

    const int tid  = threadIdx.x;
    const int lane = tid & 31;
    const int wid  = tid >> 5;
    const int wm   = wid & 3;    // 0..3: 32 M-rows each
    const int wn   = wid >> 2;   // 0..1: 32 N-cols each

    const long long aoff = blockIdx.z * STRA + (long long)(blockIdx.y * 128) * K;
    const long long boff = blockIdx.z * STRB + (long long)(blockIdx.x * 64) * K;
    Ah += aoff; Al += aoff; Bh += boff; Bl += boff;
    const long long coff = blockIdx.z * STRC +
        (long long)(blockIdx.y * 128) * LDC + blockIdx.x * 64;
    if (EPI == 0) { Cf += coff; } else { OH += coff; OL += coff; }
    if (EPI == 1) bias += blockIdx.x * 64;
    if (EPI == 2) bias += blockIdx.y * 128;

    // cp.async mapping: fixed 16B chunk column per thread
    const int lr  = tid >> 3;        // 0..31
    const int col = tid & 7;
    const uint32_t dst0 = lr * 128 + ((col * 16) ^ ((lr & 7) << 4));
    const __half* tAh = Ah + (size_t)lr * K + col * 8;
    const __half* tAl = Al + (size_t)lr * K + col * 8;
    const __half* tBh = Bh + (size_t)lr * K + col * 8;
    const __half* tBl = Bl + (size_t)lr * K + col * 8;

    auto load_stage = [&](int stage, int k0) {
        const uint32_t sb = uS + stage * STAGE_BYTES + dst0;
#pragma unroll
        for (int i = 0; i < 4; i++) {
            const size_t go = (size_t)i * 32 * K + k0;
            CP16(sb + OFF_AH + i * 4096, tAh + go);
            CP16(sb + OFF_AL + i * 4096, tAl + go);
        }
#pragma unroll
        for (int i = 0; i < 2; i++) {
            const size_t go = (size_t)i * 32 * K + k0;
            CP16(sb + OFF_BH + i * 4096, tBh + go);
            CP16(sb + OFF_BL + i * 4096, tBl + go);
        }
        CP_COMMIT();
    };

    float acc[2][4][4];
    uint32_t acc16[2][4][2];
#pragma unroll
    for (int i = 0; i < 2; i++)
#pragma unroll
        for (int j = 0; j < 4; j++) {
#pragma unroll
            for (int t = 0; t < 4; t++) acc[i][j][t] = 0.f;
            acc16[i][j][0] = 0u; acc16[i][j][1] = 0u;
        }

    constexpr int NK = K >> 6;
    load_stage(0, 0);
    if (NK > 1) load_stage(1, 64);

    const int grp  = lane >> 3;
    const int lrow = lane & 7;
    const int abase = wm * 32 + lrow + ((grp & 1) << 3);
    const int bbase = wn * 32 + lrow + ((grp & 1) << 3);

    for (int ks = 0; ks < NK; ks++) {
        if (ks + 1 < NK) CP_WAIT1(); else CP_WAIT0();
        __syncthreads();

        const uint32_t sb = uS + (ks & 1) * STAGE_BYTES;
#pragma unroll
        for (int ksub = 0; ksub < 4; ksub++) {
            const int colb = (ksub * 2 + (grp >> 1)) * 16;
            uint32_t aH[2][4], aL[2][4];
#pragma unroll
            for (int mt = 0; mt < 2; mt++) {
                const int row = abase + mt * 16;
                const uint32_t off = row * 128 + (colb ^ ((row & 7) << 4));
                LDSM4(aH[mt], sb + OFF_AH + off);
                LDSM4(aL[mt], sb + OFF_AL + off);
            }
#pragma unroll
            for (int nt4 = 0; nt4 < 2; nt4++) {
                const int brow = bbase + nt4 * 16;
                const uint32_t boff2 = brow * 128 + (colb ^ ((brow & 7) << 4));
                uint32_t bh[4], bl[4];
                LDSM4(bh, sb + OFF_BH + boff2);
                LDSM4(bl, sb + OFF_BL + boff2);
                // main pass: fp32 accumulate
#pragma unroll
                for (int mt = 0; mt < 2; mt++) {
                    MMA16816(acc[mt][nt4 * 2],     aH[mt], bh[0], bh[2]);
                    MMA16816(acc[mt][nt4 * 2 + 1], aH[mt], bh[1], bh[3]);
                }
                // correction passes: fp16 acc, mt-major so same-reg RAW >= 4 MMAs
#pragma unroll
                for (int mt = 0; mt < 2; mt++) {
                    MMA16816H(acc16[mt][nt4 * 2],     aL[mt], bh[0], bh[2]);
                    MMA16816H(acc16[mt][nt4 * 2 + 1], aL[mt], bh[1], bh[3]);
                }
#pragma unroll
                for (int mt = 0; mt < 2; mt++) {
                    MMA16816H(acc16[mt][nt4 * 2],     aH[mt], bl[0], bl[2]);
                    MMA16816H(acc16[mt][nt4 * 2 + 1], aH[mt], bl[1], bl[3]);
                }
            }
        }
        __syncthreads();
        if (ks + 2 < NK) load_stage(ks & 1, (ks + 2) * 64);
    }

    // ---- epilogue ----
#pragma unroll
    for (int mt = 0; mt < 2; mt++) {
        const int lr2 = wm * 32 + mt * 16 + (lane >> 2);
#pragma unroll
        for (int nt = 0; nt < 4; nt++) {
            const int c2 = wn * 32 + nt * 8 + (lane & 3) * 2;
            const __half2 e0 = *reinterpret_cast<__half2*>(&acc16[mt][nt][0]);
            const __half2 e1 = *reinterpret_cast<__half2*>(&acc16[mt][nt][1]);
            float v00 = acc[mt][nt][0] + __low2float(e0);
            float v01 = acc[mt][nt][1] + __high2float(e0);
            float v10 = acc[mt][nt][2] + __low2float(e1);
            float v11 = acc[mt][nt][3] + __high2float(e1);
            if (EPI == 0) {
                *reinterpret_cast<float2*>(Cf + (long long)lr2 * LDC + c2) =
                    make_float2(v00, v01);
                *reinterpret_cast<float2*>(Cf + (long long)(lr2 + 8) * LDC + c2) =
                    make_float2(v10, v11);
            } else if (EPI == 1) {
                const float b0 = bias[c2], b1 = bias[c2 + 1];
                uint32_t h, l;
                split2(v00 + b0, v01 + b1, h, l);
                *reinterpret_cast<uint32_t*>(OH + (long long)lr2 * LDC + c2) = h;
                *reinterpret_cast<uint32_t*>(OL + (long long)lr2 * LDC + c2) = l;
                split2(v10 + b0, v11 + b1, h, l);
                *reinterpret_cast<uint32_t*>(OH + (long long)(lr2 + 8) * LDC + c2) = h;
                *reinterpret_cast<uint32_t*>(OL + (long long)(lr2 + 8) * LDC + c2) = l;
            } else {
                const float b0 = bias[lr2], b1 = bias[lr2 + 8];
                float t0 = v00 + b0, t1 = v01 + b0;
                float t2 = v10 + b1, t3 = v11 + b1;
                uint32_t h, l;
                split2(t0, t1, h, l);
                *reinterpret_cast<uint32_t*>(OH + (long long)lr2 * LDC + c2) = h;
                *reinterpret_cast<uint32_t*>(OL + (long long)lr2 * LDC + c2) = l;
                split2(t0 * t0, t1 * t1, h, l);
                *reinterpret_cast<uint32_t*>(OH + (long long)(lr2 + 256) * LDC + c2) = h;
                *reinterpret_cast<uint32_t*>(OL + (long long)(lr2 + 256) * LDC + c2) = l;
                split2(t2, t3, h, l);
                *reinterpret_cast<uint32_t*>(OH + (long long)(lr2 + 8) * LDC + c2) = h;
                *reinterpret_cast<uint32_t*>(OL + (long long)(lr2 + 8) * LDC + c2) = l;
                split2(t2 * t2, t3 * t3, h, l);
                *reinterpret_cast<uint32_t*>(OH + (long long)(lr2 + 264) * LDC + c2) = h;
                *reinterpret_cast<uint32_t*>(OL + (long long)(lr2 + 264) * LDC + c2) = l;
            }
        }
    }
}

// ===========================================================================
// Transpose + split: X [b][c][p] fp32 -> Xt hi/lo [inp][b][p][c] halves.
// grid (HW/32, CC/32, 12): z -> (inp = z>>2, b = z&3). 32x32 SMEM tiles.
// ===========================================================================
__global__ __launch_bounds__(256) void tsplit_k(
    const float* __restrict__ ckey, const float* __restrict__ skey,
    const float* __restrict__ style)
{
    __shared__ float s[32][33];
    const int p = blockIdx.z >> 2;
    const int b = blockIdx.z & 3;
    const long long CHW = CHW_C;

    const float* src = (p == 0) ? ckey : (p == 1) ? skey : style;
    src += b * CHW;
    __half* dh = g_Xth + p * (BB * CHW) + b * CHW;
    __half* dl = g_Xtl + p * (BB * CHW) + b * CHW;

    const int tid = threadIdx.x;
    const int c0 = blockIdx.y * 32;
    const int p0 = blockIdx.x * 32;

    {
        const int cr = tid >> 3;
        const int pc = (tid & 7) * 4;
        float4 v = *reinterpret_cast<const float4*>(
            src + (long long)(c0 + cr) * HW + p0 + pc);
        s[cr][pc + 0] = v.x; s[cr][pc + 1] = v.y;
        s[cr][pc + 2] = v.z; s[cr][pc + 3] = v.w;
    }
    __syncthreads();
    {
        const int pr = tid >> 3;
        const int cc = (tid & 7) * 4;
        float a0 = s[cc + 0][pr], a1 = s[cc + 1][pr];
        float a2 = s[cc + 2][pr], a3 = s[cc + 3][pr];
        uint32_t h01, l01, h23, l23;
        split2(a0, a1, h01, l01);
        split2(a2, a3, h23, l23);
        const long long o = (long long)(p0 + pr) * CC + c0 + cc;
        *reinterpret_cast<uint2*>(dh + o) = make_uint2(h01, h23);
        *reinterpret_cast<uint2*>(dl + o) = make_uint2(l01, l23);
    }
}

// ---------------------------------------------------------------------------
__global__ __launch_bounds__(256) void wsplit_k(
    const float* __restrict__ Wf, const float* __restrict__ Wg,
    const float* __restrict__ Whp)
{
    const int w = blockIdx.y;
    const float* src = (w == 0) ? Wf : (w == 1) ? Wg : Whp;
    const int i4 = (blockIdx.x * 256 + threadIdx.x) * 4;
    float4 v = *reinterpret_cast<const float4*>(src + i4);
    uint32_t h01, l01, h23, l23;
    split2(v.x, v.y, h01, l01);
    split2(v.z, v.w, h23, l23);
    const int o = w * (CC * CC) + i4;
    *reinterpret_cast<uint2*>(g_Wsh + o) = make_uint2(h01, h23);
    *reinterpret_cast<uint2*>(g_Wsl + o) = make_uint2(l01, l23);
}

// ---------------------------------------------------------------------------
// Row softmax over 4096 cols for rows [rowbase, rowbase+grid).
// ---------------------------------------------------------------------------
__global__ __launch_bounds__(256) void softmax_k(int rowbase)
{
    __shared__ float red[8];
    const size_t row = rowbase + blockIdx.x;
    const float4* p = reinterpret_cast<const float4*>(g_S + row * (size_t)HW);
    uint2* ph = reinterpret_cast<uint2*>(g_Sh + row * (size_t)HW);
    uint2* pl = reinterpret_cast<uint2*>(g_Sl + row * (size_t)HW);
    const int tid = threadIdx.x;

    float4 v[4];
    float mx = -3.4e38f;
#pragma unroll
    for (int i = 0; i < 4; i++) {
        v[i] = p[tid + i * 256];
        mx = fmaxf(mx, fmaxf(fmaxf(v[i].x, v[i].y), fmaxf(v[i].z, v[i].w)));
    }
#pragma unroll
    for (int o = 16; o > 0; o >>= 1)
        mx = fmaxf(mx, __shfl_xor_sync(0xffffffffu, mx, o));
    if ((tid & 31) == 0) red[tid >> 5] = mx;
    __syncthreads();
    mx = red[0];
#pragma unroll
    for (int i = 1; i < 8; i++) mx = fmaxf(mx, red[i]);

    float s = 0.f;
#pragma unroll
    for (int i = 0; i < 4; i++) {
        v[i].x = __expf(v[i].x - mx); v[i].y = __expf(v[i].y - mx);
        v[i].z = __expf(v[i].z - mx); v[i].w = __expf(v[i].w - mx);
        s += v[i].x + v[i].y + v[i].z + v[i].w;
    }
#pragma unroll
    for (int o = 16; o > 0; o >>= 1)
        s += __shfl_xor_sync(0xffffffffu, s, o);
    __syncthreads();
    if ((tid & 31) == 0) red[tid >> 5] = s;
    __syncthreads();
    s = red[0];
#pragma unroll
    for (int i = 1; i < 8; i++) s += red[i];

    const float inv = 1.0f / s;
#pragma unroll
    for (int i = 0; i < 4; i++) {
        float w0 = v[i].x * inv, w1 = v[i].y * inv;
        float w2 = v[i].z * inv, w3 = v[i].w * inv;
        uint32_t h01, l01, h23, l23;
        split2(w0, w1, h01, l01);
        split2(w2, w3, h23, l23);
        ph[tid + i * 256] = make_uint2(h01, h23);
        pl[tid + i * 256] = make_uint2(l01, l23);
    }
}

// ---------------------------------------------------------------------------
__global__ __launch_bounds__(256) void stats_k(const float* __restrict__ content)
{
    __shared__ float r1[8];
    __shared__ float r2[8];
    const int bc = blockIdx.x;
    const float4* p = reinterpret_cast<const float4*>(content + (size_t)bc * HW);
    const int tid = threadIdx.x;

    float s = 0.f, s2 = 0.f;
#pragma unroll
    for (int i = 0; i < 4; i++) {
        float4 v = p[tid + i * 256];
        s  += v.x + v.y + v.z + v.w;
        s2 += v.x * v.x + v.y * v.y + v.z * v.z + v.w * v.w;
    }
#pragma unroll
    for (int o = 16; o > 0; o >>= 1) {
        s  += __shfl_xor_sync(0xffffffffu, s, o);
        s2 += __shfl_xor_sync(0xffffffffu, s2, o);
    }
    if ((tid & 31) == 0) { r1[tid >> 5] = s; r2[tid >> 5] = s2; }
    __syncthreads();
    if (tid == 0) {
        float ts = 0.f, ts2 = 0.f;
#pragma unroll
        for (int i = 0; i < 8; i++) { ts += r1[i]; ts2 += r2[i]; }
        float mean = ts * (1.0f / HW);
        float var  = (ts2 - (float)HW * mean * mean) * (1.0f / (HW - 1));
        g_cmean[bc] = mean;
        g_cinv[bc]  = rsqrtf(var + 1e-5f);
    }
}

// ---------------------------------------------------------------------------
// Fused modulation, tiled transpose for coalesced ME reads and out writes.
// grid (HW/128, CC/32, BB), block 256.
// ---------------------------------------------------------------------------
__global__ __launch_bounds__(256) void final_k(const float* __restrict__ content,
                                               float* __restrict__ out)
{
    __shared__ float sM[128][33];
    __shared__ float sE[128][33];
    const int tid = threadIdx.x;
    const int b  = blockIdx.z;
    const int c0 = blockIdx.y * 32;
    const int n0 = blockIdx.x * 128;

    const float* base = g_ME + ((size_t)(b * HW + n0)) * (2 * CC) + c0;
    const int nl0 = tid >> 3;
    const int cq  = (tid & 7) * 4;
#pragma unroll
    for (int i = 0; i < 4; i++) {
        const int n = nl0 + i * 32;
        float4 m = *reinterpret_cast<const float4*>(base + (size_t)n * (2 * CC) + cq);
        float4 e = *reinterpret_cast<const float4*>(base + (size_t)n * (2 * CC) + CC + cq);
        sM[n][cq + 0] = m.x; sM[n][cq + 1] = m.y; sM[n][cq + 2] = m.z; sM[n][cq + 3] = m.w;
        sE[n][cq + 0] = e.x; sE[n][cq + 1] = e.y; sE[n][cq + 2] = e.z; sE[n][cq + 3] = e.w;
    }
    __syncthreads();

#pragma unroll
    for (int j = 0; j < 16; j++) {
        const int e  = j * 256 + tid;
        const int cl = e >> 7;
        const int nl = e & 127;
        const int c  = c0 + cl;
        const int bc = b * CC + c;
        const size_t oidx = ((size_t)bc) * HW + n0 + nl;
        const float m  = sM[nl][cl];
        const float e2 = sE[nl][cl];
        const float sd = sqrtf(fmaxf(e2 - m * m, 0.f));
        out[oidx] = sd * (content[oidx] - g_cmean[bc]) * g_cinv[bc] + m;
    }
}

// ---------------------------------------------------------------------------
extern "C" void kernel_launch(void* const* d_in, const int* in_sizes, int n_in,
                              void* d_out, int out_size)
{
    const float* content = (const float*)d_in[0];
    const float* style   = (const float*)d_in[1];
    const float* ckey    = (const float*)d_in[2];
    const float* skey    = (const float*)d_in[3];
    const float* Wf = (const float*)d_in[4];
    const float* bf = (const float*)d_in[5];
    const float* Wg = (const float*)d_in[6];
    const float* bg = (const float*)d_in[7];
    const float* Wh = (const float*)d_in[8];
    const float* bh = (const float*)d_in[9];
    float* out = (float*)d_out;

    __half *Xth, *Xtl, *Wsh, *Wsl;
    __half *Qh, *Ql, *Kth, *Ktl, *VVth, *VVtl, *Sh, *Sl;
    float *S, *ME;
    cudaGetSymbolAddress((void**)&Xth, g_Xth);
    cudaGetSymbolAddress((void**)&Xtl, g_Xtl);
    cudaGetSymbolAddress((void**)&Wsh, g_Wsh);
    cudaGetSymbolAddress((void**)&Wsl, g_Wsl);
    cudaGetSymbolAddress((void**)&Qh,  g_Qh);
    cudaGetSymbolAddress((void**)&Ql,  g_Ql);
    cudaGetSymbolAddress((void**)&Kth, g_Kth);
    cudaGetSymbolAddress((void**)&Ktl, g_Ktl);
    cudaGetSymbolAddress((void**)&VVth, g_VVth);
    cudaGetSymbolAddress((void**)&VVtl, g_VVtl);
    cudaGetSymbolAddress((void**)&Sh,  g_Sh);
    cudaGetSymbolAddress((void**)&Sl,  g_Sl);
    cudaGetSymbolAddress((void**)&S,   g_S);
    cudaGetSymbolAddress((void**)&ME,  g_ME);

    // Instantiations: <EPI, K, LDC, strA, strB, strC>
    auto kProj = hmma6<1, CC, CC, CHW_C, 0LL, CHW_C>;
    auto kVVt  = hmma6<2, CC, HW, 0LL, CHW_C, 2 * CHW_C>;
    auto kG1   = hmma6<0, CC, HW, CHW_C, CHW_C, SHW_C>;
    auto kG2   = hmma6<0, HW, 2 * CC, SHW_C, 2 * CHW_C, MEW_C>;

    // One-time setup (runs on the uncaptured correctness call).
    static cudaStream_t s1 = nullptr;
    static cudaEvent_t evFork = nullptr, evK = nullptr, evG1 = nullptr;
    static cudaEvent_t evSide = nullptr, evDone = nullptr;
    if (s1 == nullptr) {
        cudaStreamCreateWithFlags(&s1, cudaStreamNonBlocking);
        cudaEventCreateWithFlags(&evFork, cudaEventDisableTiming);
        cudaEventCreateWithFlags(&evK,    cudaEventDisableTiming);
        cudaEventCreateWithFlags(&evG1,   cudaEventDisableTiming);
        cudaEventCreateWithFlags(&evSide, cudaEventDisableTiming);
        cudaEventCreateWithFlags(&evDone, cudaEventDisableTiming);
        cudaFuncSetAttribute(kProj, cudaFuncAttributeMaxDynamicSharedMemorySize,
                             2 * STAGE_BYTES);
        cudaFuncSetAttribute(kVVt, cudaFuncAttributeMaxDynamicSharedMemorySize,
                             2 * STAGE_BYTES);
        cudaFuncSetAttribute(kG1, cudaFuncAttributeMaxDynamicSharedMemorySize,
                             2 * STAGE_BYTES);
        cudaFuncSetAttribute(kG2, cudaFuncAttributeMaxDynamicSharedMemorySize,
                             2 * STAGE_BYTES);
    }

    const dim3 blk(256);
    const long long BCHW = (long long)BB * CHW_C;

    // ---- s0: input transpose+split and weight split ----
    tsplit_k<<<dim3(HW / 32, CC / 32, 12), blk>>>(ckey, skey, style);
    wsplit_k<<<dim3(64, 3), blk>>>(Wf, Wg, Wh);
    cudaEventRecord(evFork, 0);

    // ---- s1 (forked): Kt proj -> VVt proj -> content stats ----
    cudaStreamWaitEvent(s1, evFork, 0);
    kProj<<<dim3(4, 32, BB), blk, 2 * STAGE_BYTES, s1>>>(
        Xth + BCHW, Xtl + BCHW, Wsh + CC * CC, Wsl + CC * CC,
        nullptr, Kth, Ktl, bg);
    cudaEventRecord(evK, s1);
    kVVt<<<dim3(64, 2, BB), blk, 2 * STAGE_BYTES, s1>>>(
        Wsh + 2 * CC * CC, Wsl + 2 * CC * CC, Xth + 2 * BCHW, Xtl + 2 * BCHW,
        nullptr, VVth, VVtl, bh);
    stats_k<<<BB * CC, blk, 0, s1>>>(content);
    cudaEventRecord(evSide, s1);

    // ---- s0: Q proj, then monolithic GEMM1 (needs Kt from s1) ----
    kProj<<<dim3(4, 32, BB), blk, 2 * STAGE_BYTES>>>(
        Xth, Xtl, Wsh, Wsl, nullptr, Qh, Ql, bf);
    cudaStreamWaitEvent(0, evK, 0);

    // GEMM1: S[n,m] = Q[n,:] . Kt[m,:]   (M=4096,N=4096,K=256) — monolithic
    kG1<<<dim3(64, 32, BB), blk, 2 * STAGE_BYTES>>>(
        Qh, Ql, Kth, Ktl, S, nullptr, nullptr, nullptr);
    cudaEventRecord(evG1, 0);

    // VVt ready needed by GEMM2 on both streams
    cudaStreamWaitEvent(0, evSide, 0);
    cudaStreamWaitEvent(s1, evG1, 0);

    // ---- per-batch softmax -> GEMM2, alternating streams ----
    // s0: b0, b2;  s1: b1, b3.  Softmax of one batch hides under the other
    // stream's GEMM2; per-batch G2 (256 CTAs) pairs co-run.
    for (int b = 0; b < BB; b++) {
        cudaStream_t sb = (b & 1) ? s1 : (cudaStream_t)0;
        softmax_k<<<HW, blk, 0, sb>>>(b * HW);
        kG2<<<dim3(8, 32, 1), blk, 2 * STAGE_BYTES, sb>>>(
            Sh + b * SHW_C, Sl + b * SHW_C,
            VVth + b * 2 * CHW_C, VVtl + b * 2 * CHW_C,
            ME + b * MEW_C, nullptr, nullptr, nullptr);
    }

    // join s1 -> s0, then fused modulation
    cudaEventRecord(evDone, s1);
    cudaStreamWaitEvent(0, evDone, 0);
    final_k<<<dim3(HW / 128, CC / 32, BB), blk>>>(content, out);
}